// round 4
// baseline (speedup 1.0000x reference)
#include <cuda_runtime.h>
#include <cstdint>

#define D 1024
#define WARPS 4          // warps per block
#define RPW 2            // rows per warp (packed into u64 smem slots)

typedef unsigned long long u64;

// ---------- packed f32x2 helpers (sm_103a) ----------
__device__ __forceinline__ u64 pack2(float a, float b) {
    u64 r; asm("mov.b64 %0, {%1, %2};" : "=l"(r) : "f"(a), "f"(b)); return r;
}
__device__ __forceinline__ void unpack2(u64 v, float& a, float& b) {
    asm("mov.b64 {%0, %1}, %2;" : "=f"(a), "=f"(b) : "l"(v));
}
__device__ __forceinline__ u64 add2(u64 a, u64 b) {
    u64 r; asm("add.rn.f32x2 %0, %1, %2;" : "=l"(r) : "l"(a), "l"(b)); return r;
}
__device__ __forceinline__ u64 mul2(u64 a, u64 b) {
    u64 r; asm("mul.rn.f32x2 %0, %1, %2;" : "=l"(r) : "l"(a), "l"(b)); return r;
}
__device__ __forceinline__ u64 fma2(u64 a, u64 b, u64 c) {
    u64 r; asm("fma.rn.f32x2 %0, %1, %2, %3;" : "=l"(r) : "l"(a), "l"(b), "l"(c)); return r;
}

// In-register FWHT over the 32-element register axis (pack k = axis values 2k,2k+1)
__device__ __forceinline__ void fwht32(u64 v[16]) {
    const u64 NEG1 = 0xBF800000BF800000ULL;  // (-1.f, -1.f)
    #pragma unroll
    for (int k = 0; k < 16; k++) {
        float a, b; unpack2(v[k], a, b);
        v[k] = pack2(a + b, a - b);
    }
    #pragma unroll
    for (int h = 1; h <= 8; h <<= 1) {
        #pragma unroll
        for (int k = 0; k < 16; k++) {
            if (!(k & h)) {
                u64 A = v[k], B = v[k + h];
                v[k]     = add2(A, B);
                v[k + h] = fma2(B, NEG1, A);
            }
        }
    }
}

// FWHT over the 32-lane axis via butterfly shuffles (no smem traffic).
// Lane with bit h clear gets (a+b); lane with bit h set gets (a-b):
//   v_new = partner + sgn*v,  sgn = +1 if (lane&h)==0 else -1.
__device__ __forceinline__ void fwht_lane(u64 v[16], const u64 sgn[5]) {
    #pragma unroll
    for (int s = 0; s < 5; s++) {
        #pragma unroll
        for (int k = 0; k < 16; k++) {
            u64 o = __shfl_xor_sync(0xffffffffu, v[k], 1 << s);
            v[k] = fma2(v[k], sgn[s], o);
        }
    }
}

// Physical u64 slot (per warp buffer) for destination element t.
// Layout: owner lane L = t&31 holds its 32 values contiguously (16 float4),
// with float4-column XOR swizzle so the gather LDS.128s are conflict-free.
__device__ __forceinline__ int slot_of(int t) {
    int L = t & 31, c = t >> 5;
    return L * 32 + ((((c >> 1) ^ (L & 7)) & 15) << 1) + (c & 1);
}

// Precomputed tables (allocation-free scratch)
__device__ int   g_Qt[D];   // Qt[e] = slot_of(Pinv[e])  (scatter targets, e-natural layout)
__device__ float g_Gt[D];   // Gt[(t&31)*32 + (t>>5)] = G[t]
__device__ float g_St[D];   // St[(t&31)*32 + (t>>5)] = S[t]/32

__global__ void fastfood_prep(const int* __restrict__ P, const float* __restrict__ G,
                              const float* __restrict__ S) {
    int i = blockIdx.x * blockDim.x + threadIdx.x;   // i = t
    if (i < D) {
        g_Qt[P[i]] = slot_of(i);                     // P[t] = e  ->  Qt[e] = slot(t)
        g_Gt[(i & 31) * 32 + (i >> 5)] = G[i];
        g_St[(i & 31) * 32 + (i >> 5)] = S[i] * 0.03125f;  // 1/sqrt(1024), SCALE=1
    }
}

__global__ __launch_bounds__(WARPS * 32, 4)
void fastfood_kernel(const float* __restrict__ x, const float* __restrict__ B,
                     float* __restrict__ out, int nrows) {
    __shared__ u64 buf[WARPS][D];      // 32 KB/block: one u64 slot per element, 2 rows packed
    const int warp = threadIdx.x >> 5;
    const int lane = threadIdx.x & 31;
    const int pair = blockIdx.x * WARPS + warp;
    if (pair * RPW >= nrows) return;

    u64* sb = buf[warp];
    const float4* sb4 = reinterpret_cast<const float4*>(sb);

    // per-lane sign packs for the shuffle butterflies
    u64 sgn[5];
    #pragma unroll
    for (int s = 0; s < 5; s++) {
        float f = (lane & (1 << s)) ? -1.0f : 1.0f;
        sgn[s] = pack2(f, f);
    }

    u64 va[16], vb[16];

    // ---- load x*B: lane owns e = lane*32 + k (float4, coalesced) ----
    const float4* Bv = reinterpret_cast<const float4*>(B) + lane * 8;
    const float4* xa = reinterpret_cast<const float4*>(x) + (size_t)(pair * RPW) * (D / 4) + lane * 8;
    const float4* xb = xa + (D / 4);
    #pragma unroll
    for (int c4 = 0; c4 < 8; c4++) {
        float4 bb = Bv[c4];
        float4 fa = xa[c4];
        float4 fb = xb[c4];
        u64 b01 = pack2(bb.x, bb.y), b23 = pack2(bb.z, bb.w);
        va[2*c4]   = mul2(pack2(fa.x, fa.y), b01);
        va[2*c4+1] = mul2(pack2(fa.z, fa.w), b23);
        vb[2*c4]   = mul2(pack2(fb.x, fb.y), b01);
        vb[2*c4+1] = mul2(pack2(fb.z, fb.w), b23);
    }

    // ---- WHT #1: low axis (k, registers) + high axis (lane, shuffles) ----
    fwht32(va); fwht32(vb);
    fwht_lane(va, sgn); fwht_lane(vb, sgn);

    // ---- permutation: scatter HBx[e] (both rows packed) to slot of t = Pinv[e] ----
    const int4* Q4 = reinterpret_cast<const int4*>(g_Qt) + lane * 8;
    #pragma unroll
    for (int c4 = 0; c4 < 8; c4++) {
        int4 q = Q4[c4];        // targets for e = lane*32 + 4c4 .. +3
        float a0, a1, a2, a3, b0, b1, b2, b3;
        unpack2(va[2*c4],   a0, a1);
        unpack2(va[2*c4+1], a2, a3);
        unpack2(vb[2*c4],   b0, b1);
        unpack2(vb[2*c4+1], b2, b3);
        sb[q.x] = pack2(a0, b0);
        sb[q.y] = pack2(a1, b1);
        sb[q.z] = pack2(a2, b2);
        sb[q.w] = pack2(a3, b3);
    }
    __syncwarp();

    // ---- gather: lane owns t = c*32 + lane (16 conflict-free LDS.128) ----
    #pragma unroll
    for (int j = 0; j < 16; j++) {
        float4 f = sb4[lane * 16 + (j ^ (lane & 7))];   // u64 pair {c=2j, c=2j+1}
        va[j] = pack2(f.x, f.z);
        vb[j] = pack2(f.y, f.w);
    }

    // ---- multiply G (transposed table, float4) ----
    const float4* Gv = reinterpret_cast<const float4*>(g_Gt) + lane * 8;
    #pragma unroll
    for (int c4 = 0; c4 < 8; c4++) {
        float4 g = Gv[c4];
        u64 g01 = pack2(g.x, g.y), g23 = pack2(g.z, g.w);
        va[2*c4]   = mul2(va[2*c4],   g01);
        va[2*c4+1] = mul2(va[2*c4+1], g23);
        vb[2*c4]   = mul2(vb[2*c4],   g01);
        vb[2*c4+1] = mul2(vb[2*c4+1], g23);
    }

    // ---- WHT #2: high axis (c, registers) + low axis (lane, shuffles) ----
    fwht32(va); fwht32(vb);
    fwht_lane(va, sgn); fwht_lane(vb, sgn);

    // ---- scale by S/32 (transposed table) and store coalesced scalar ----
    const float4* Sv = reinterpret_cast<const float4*>(g_St) + lane * 8;
    float* oa = out + (size_t)(pair * RPW) * D;
    float* ob = oa + D;
    #pragma unroll
    for (int c4 = 0; c4 < 8; c4++) {
        float4 s = Sv[c4];
        u64 s01 = pack2(s.x, s.y), s23 = pack2(s.z, s.w);
        u64 ra0 = mul2(va[2*c4],   s01);
        u64 ra1 = mul2(va[2*c4+1], s23);
        u64 rb0 = mul2(vb[2*c4],   s01);
        u64 rb1 = mul2(vb[2*c4+1], s23);
        float p0, p1, p2, p3;
        unpack2(ra0, p0, p1); unpack2(ra1, p2, p3);
        oa[(4*c4+0)*32 + lane] = p0;
        oa[(4*c4+1)*32 + lane] = p1;
        oa[(4*c4+2)*32 + lane] = p2;
        oa[(4*c4+3)*32 + lane] = p3;
        unpack2(rb0, p0, p1); unpack2(rb1, p2, p3);
        ob[(4*c4+0)*32 + lane] = p0;
        ob[(4*c4+1)*32 + lane] = p1;
        ob[(4*c4+2)*32 + lane] = p2;
        ob[(4*c4+3)*32 + lane] = p3;
    }
}

extern "C" void kernel_launch(void* const* d_in, const int* in_sizes, int n_in,
                              void* d_out, int out_size) {
    const float* x = (const float*)d_in[0];
    const float* B = (const float*)d_in[1];
    const float* G = (const float*)d_in[2];
    const float* S = (const float*)d_in[3];
    const int*   P = (const int*)d_in[4];
    float* out = (float*)d_out;

    const int nrows = in_sizes[0] / D;

    fastfood_prep<<<(D + 255) / 256, 256>>>(P, G, S);

    const int rows_per_block = WARPS * RPW;
    const int blocks = (nrows + rows_per_block - 1) / rows_per_block;
    fastfood_kernel<<<blocks, WARPS * 32>>>(x, B, out, nrows);
}

// round 6
// speedup vs baseline: 2.3076x; 2.3076x over previous
#include <cuda_runtime.h>
#include <cstdint>

#define D 1024
#define WARPS 4          // warps per block (128 threads), 1 row per warp

typedef unsigned long long u64;

// ---------- packed f32x2 helpers (sm_103a) ----------
__device__ __forceinline__ u64 pack2(float a, float b) {
    u64 r; asm("mov.b64 %0, {%1, %2};" : "=l"(r) : "f"(a), "f"(b)); return r;
}
__device__ __forceinline__ void unpack2(u64 v, float& a, float& b) {
    asm("mov.b64 {%0, %1}, %2;" : "=f"(a), "=f"(b) : "l"(v));
}
__device__ __forceinline__ u64 add2(u64 a, u64 b) {
    u64 r; asm("add.rn.f32x2 %0, %1, %2;" : "=l"(r) : "l"(a), "l"(b)); return r;
}
__device__ __forceinline__ u64 mul2(u64 a, u64 b) {
    u64 r; asm("mul.rn.f32x2 %0, %1, %2;" : "=l"(r) : "l"(a), "l"(b)); return r;
}
__device__ __forceinline__ u64 fma2(u64 a, u64 b, u64 c) {
    u64 r; asm("fma.rn.f32x2 %0, %1, %2, %3;" : "=l"(r) : "l"(a), "l"(b), "l"(c)); return r;
}

// FWHT over the 32-value register axis. v[k] packs index i = 2k (lo), 2k+1 (hi).
// The i-bit -> element-bit mapping is the caller's choice (H factorizes per bit).
__device__ __forceinline__ void fwht32(u64 v[16]) {
    const u64 NEG1 = 0xBF800000BF800000ULL;  // (-1.f, -1.f)
    #pragma unroll
    for (int k = 0; k < 16; k++) {
        float a, b; unpack2(v[k], a, b);
        v[k] = pack2(a + b, a - b);
    }
    #pragma unroll
    for (int h = 1; h <= 8; h <<= 1) {
        #pragma unroll
        for (int k = 0; k < 16; k++) {
            if (!(k & h)) {
                u64 A = v[k], B = v[k + h];
                v[k]     = add2(A, B);
                v[k + h] = fma2(B, NEG1, A);
            }
        }
    }
}

// Bit roles for an index z (10 bits), "QB ownership":  lane = (z>>7)*4 + (z&3),
// register m = (z>>2)&31.  Crossings move between QB ownership and
// "natural ownership" (lane' owns z = q*128 + 4*lane' + b, regs i = b|(q<<2)).

// Precomputed tables (allocation-free scratch), all laid out for coalesced
// vector reads at index [j*32 + lane]:
__device__ int   g_Qt[D];   // scatter targets for writer (lane w, reg mw) of e
__device__ float g_Gt[D];   // G[t] for gather owner (lane L, reg mm) of t
__device__ float g_St[D];   // S[t]/32, natural order

__global__ void fastfood_prep(const int* __restrict__ P, const float* __restrict__ G,
                              const float* __restrict__ S) {
    int t = blockIdx.x * blockDim.x + threadIdx.x;
    if (t < D) {
        int e  = P[t];
        int w  = ((e >> 7) << 2) | (e & 3);   // writer lane of e (QB ownership)
        int mw = (e >> 2) & 31;               // writer reg of e
        int L  = ((t >> 7) << 2) | (t & 3);   // gather owner lane of t
        int mm = (t >> 2) & 31;               // gather reg of t
        // scatter slot: lane L's 32 values contiguous, float4-XOR swizzled
        int slot = L * 32 + ((((mm >> 2) ^ (L & 7)) & 7) << 2) + (mm & 3);
        g_Qt[(mw >> 2) * 128 + w * 4 + (mw & 3)] = slot;   // int4 idx (mw>>2)*32+w
        g_Gt[(mm >> 2) * 128 + L * 4 + (mm & 3)] = G[t];   // f4  idx (mm>>2)*32+L
        g_St[t] = S[t] * 0.03125f;   // 1/sqrt(1024), SCALE=1
    }
}

__global__ __launch_bounds__(WARPS * 32, 6)
void fastfood_kernel(const float* __restrict__ x, const float* __restrict__ B,
                     float* __restrict__ out, int nrows) {
    __shared__ float buf[WARPS][D];   // 16 KB/block, one buffer per warp
    const int warp = threadIdx.x >> 5;
    const int lane = threadIdx.x & 31;
    const int row  = blockIdx.x * WARPS + warp;
    if (row >= nrows) return;

    float* sA = buf[warp];
    float4* sA4 = reinterpret_cast<float4*>(sA);
    const int qr = lane >> 2, br = lane & 3;

    u64 v[16];

    // ---- load x*B: natural ownership of e, regs i = e-bits {0,1,7,8,9} ----
    const float4* xv = reinterpret_cast<const float4*>(x) + (size_t)row * (D / 4) + lane;
    const float4* Bv = reinterpret_cast<const float4*>(B) + lane;
    #pragma unroll
    for (int q = 0; q < 8; q++) {
        float4 f = xv[q * 32];
        float4 b = Bv[q * 32];
        v[2*q]   = mul2(pack2(f.x, f.y), pack2(b.x, b.y));
        v[2*q+1] = mul2(pack2(f.z, f.w), pack2(b.z, b.w));
    }

    // ---- WHT#1a over e-bits {0,1,7,8,9} ----
    fwht32(v);

    // ---- crossing 1: natural -> QB ownership (regs become e-bits {2..6}) ----
    #pragma unroll
    for (int q = 0; q < 8; q++) {
        float a0, a1, a2, a3;
        unpack2(v[2*q],   a0, a1);
        unpack2(v[2*q+1], a2, a3);
        sA4[q * 32 + (lane ^ q)] = make_float4(a0, a1, a2, a3);   // conflict-free
    }
    __syncwarp();
    {
        const float* base = sA + qr * 128 + br;
        #pragma unroll
        for (int k = 0; k < 16; k++) {
            float a = base[((2*k)     ^ qr) << 2];   // conflict-free scalar reads
            float b = base[((2*k + 1) ^ qr) << 2];
            v[k] = pack2(a, b);
        }
    }

    // ---- WHT#1b over e-bits {2..6}: HBx complete ----
    fwht32(v);
    __syncwarp();   // all crossing-1 reads done before scatter overwrites

    // ---- crossing 2 (permutation): scatter HBx[e] to gather slot of t, P[t]=e ----
    const int4* Q4 = reinterpret_cast<const int4*>(g_Qt);
    #pragma unroll
    for (int j = 0; j < 8; j++) {
        int4 q = Q4[j * 32 + lane];            // targets for mw = 4j .. 4j+3
        float a0, a1, a2, a3;
        unpack2(v[2*j],   a0, a1);
        unpack2(v[2*j+1], a2, a3);
        sA[q.x] = a0; sA[q.y] = a1; sA[q.z] = a2; sA[q.w] = a3;
    }
    __syncwarp();

    // ---- gather (QB ownership of t, regs = t-bits {2..6}), multiply G ----
    const float4* Gv = reinterpret_cast<const float4*>(g_Gt);
    #pragma unroll
    for (int j = 0; j < 8; j++) {
        float4 f = sA4[lane * 8 + ((j ^ lane) & 7)];   // conflict-free LDS.128
        float4 g = Gv[j * 32 + lane];                  // coalesced
        v[2*j]   = mul2(pack2(f.x, f.y), pack2(g.x, g.y));
        v[2*j+1] = mul2(pack2(f.z, f.w), pack2(g.z, g.w));
    }

    // ---- WHT#2a over t-bits {2..6} ----
    fwht32(v);
    __syncwarp();   // gather reads done before crossing-3 writes

    // ---- crossing 3: QB -> natural ownership (regs become t-bits {0,1,7,8,9}) ----
    {
        float* base = sA + qr * 128 + br;
        #pragma unroll
        for (int k = 0; k < 16; k++) {
            float a, b; unpack2(v[k], a, b);
            base[((2*k)     ^ qr) << 2] = a;   // conflict-free scalar writes
            base[((2*k + 1) ^ qr) << 2] = b;
        }
    }
    __syncwarp();
    #pragma unroll
    for (int q = 0; q < 8; q++) {
        float4 f = sA4[q * 32 + (lane ^ q)];   // conflict-free LDS.128
        v[2*q]   = pack2(f.x, f.y);
        v[2*q+1] = pack2(f.z, f.w);
    }

    // ---- WHT#2b over t-bits {0,1,7,8,9}: transform complete ----
    fwht32(v);

    // ---- x S/32 (natural table) and coalesced float4 stores ----
    const float4* Sv = reinterpret_cast<const float4*>(g_St) + lane;
    float4* ov = reinterpret_cast<float4*>(out) + (size_t)row * (D / 4) + lane;
    #pragma unroll
    for (int q = 0; q < 8; q++) {
        float4 s = Sv[q * 32];
        u64 r0 = mul2(v[2*q],   pack2(s.x, s.y));
        u64 r1 = mul2(v[2*q+1], pack2(s.z, s.w));
        float p0, p1, p2, p3;
        unpack2(r0, p0, p1);
        unpack2(r1, p2, p3);
        ov[q * 32] = make_float4(p0, p1, p2, p3);
    }
}

extern "C" void kernel_launch(void* const* d_in, const int* in_sizes, int n_in,
                              void* d_out, int out_size) {
    const float* x = (const float*)d_in[0];
    const float* B = (const float*)d_in[1];
    const float* G = (const float*)d_in[2];
    const float* S = (const float*)d_in[3];
    const int*   P = (const int*)d_in[4];
    float* out = (float*)d_out;

    const int nrows = in_sizes[0] / D;

    fastfood_prep<<<(D + 255) / 256, 256>>>(P, G, S);

    const int blocks = (nrows + WARPS - 1) / WARPS;
    fastfood_kernel<<<blocks, WARPS * 32>>>(x, B, out, nrows);
}

// round 7
// speedup vs baseline: 2.4902x; 1.0791x over previous
#include <cuda_runtime.h>
#include <cstdint>

#define D 1024
#define WARPS 4          // warps per block (128 threads), 1 row per warp

typedef unsigned long long u64;

// ---------- packed f32x2 helpers (sm_103a) ----------
__device__ __forceinline__ u64 pack2(float a, float b) {
    u64 r; asm("mov.b64 %0, {%1, %2};" : "=l"(r) : "f"(a), "f"(b)); return r;
}
__device__ __forceinline__ void unpack2(u64 v, float& a, float& b) {
    asm("mov.b64 {%0, %1}, %2;" : "=f"(a), "=f"(b) : "l"(v));
}
__device__ __forceinline__ u64 add2(u64 a, u64 b) {
    u64 r; asm("add.rn.f32x2 %0, %1, %2;" : "=l"(r) : "l"(a), "l"(b)); return r;
}
__device__ __forceinline__ u64 mul2(u64 a, u64 b) {
    u64 r; asm("mul.rn.f32x2 %0, %1, %2;" : "=l"(r) : "l"(a), "l"(b)); return r;
}
__device__ __forceinline__ u64 fma2(u64 a, u64 b, u64 c) {
    u64 r; asm("fma.rn.f32x2 %0, %1, %2, %3;" : "=l"(r) : "l"(a), "l"(b), "l"(c)); return r;
}

// FWHT over the 32-value register axis. v[k] packs index i = 2k (lo), 2k+1 (hi).
// The i-bit -> element-bit mapping is the caller's choice (H factorizes per bit).
__device__ __forceinline__ void fwht32(u64 v[16]) {
    const u64 NEG1 = 0xBF800000BF800000ULL;  // (-1.f, -1.f)
    #pragma unroll
    for (int k = 0; k < 16; k++) {
        float a, b; unpack2(v[k], a, b);
        v[k] = pack2(a + b, a - b);
    }
    #pragma unroll
    for (int h = 1; h <= 8; h <<= 1) {
        #pragma unroll
        for (int k = 0; k < 16; k++) {
            if (!(k & h)) {
                u64 A = v[k], B = v[k + h];
                v[k]     = add2(A, B);
                v[k + h] = fma2(B, NEG1, A);
            }
        }
    }
}

// Bit roles for an index z (10 bits), "QB ownership":  lane = (z>>7)*4 + (z&3),
// register m = (z>>2)&31.  Crossings move between QB ownership and
// "natural ownership" (lane' owns z = q*128 + 4*lane' + b, regs i = b|(q<<2)).

// Precomputed tables (allocation-free scratch):
__device__ unsigned short g_Qs[D];  // scatter targets (u16 slots), writer-layout for uint4 loads
__device__ float          g_Gt[D];  // G[t] for gather owner (lane L, reg mm) of t
__device__ float          g_St[D];  // S[t]/32, natural order
__device__ unsigned       g_Bbits[32];  // sign bits of B, natural ownership: bit 4q+b for lane

__global__ void fastfood_prep(const int* __restrict__ P, const float* __restrict__ B,
                              const float* __restrict__ G, const float* __restrict__ S) {
    int t = blockIdx.x * blockDim.x + threadIdx.x;
    if (t < D) {
        int e  = P[t];
        int w  = ((e >> 7) << 2) | (e & 3);   // writer lane of e (QB ownership)
        int mw = (e >> 2) & 31;               // writer reg of e
        int L  = ((t >> 7) << 2) | (t & 3);   // gather owner lane of t
        int mm = (t >> 2) & 31;               // gather reg of t
        // scatter slot: lane L's 32 values contiguous, float4-XOR swizzled (fits u16)
        int slot = L * 32 + ((((mm >> 2) ^ (L & 7)) & 7) << 2) + (mm & 3);
        // u16 table layout: uint4 load j' = mw>>3 at [j'*32 + w] covers mw = 8j'..8j'+7
        g_Qs[(mw >> 3) * 256 + w * 8 + (mw & 7)] = (unsigned short)slot;
        g_Gt[(mm >> 2) * 128 + L * 4 + (mm & 3)] = G[t];   // f4 idx (mm>>2)*32+L
        g_St[t] = S[t] * 0.03125f;   // 1/sqrt(1024), SCALE=1
    }
    // B sign bitmask, natural ownership: lane owns e = q*128 + 4*lane + b, bit p = 4q+b
    if (t < 32) {
        unsigned bits = 0;
        for (int q = 0; q < 8; q++)
            for (int b = 0; b < 4; b++)
                if (B[q * 128 + 4 * t + b] < 0.0f) bits |= 1u << (4 * q + b);
        g_Bbits[t] = bits;
    }
}

__global__ __launch_bounds__(WARPS * 32, 6)
void fastfood_kernel(const float* __restrict__ x, float* __restrict__ out, int nrows) {
    __shared__ float buf[WARPS][D];   // 16 KB/block, one buffer per warp
    const int warp = threadIdx.x >> 5;
    const int lane = threadIdx.x & 31;
    const int row  = blockIdx.x * WARPS + warp;
    if (row >= nrows) return;

    float* sA = buf[warp];
    float4* sA4 = reinterpret_cast<float4*>(sA);
    const int qr = lane >> 2, br = lane & 3;

    const unsigned bb = g_Bbits[lane];   // sign mask for this lane's 32 elements

    u64 v[16];

    // ---- load x, apply B as sign-bit XOR (natural ownership of e) ----
    const float4* xv = reinterpret_cast<const float4*>(x) + (size_t)row * (D / 4) + lane;
    #pragma unroll
    for (int q = 0; q < 8; q++) {
        float4 f = xv[q * 32];
        u64 m0 = (((u64)((bb >> (4*q + 0)) & 1u)) << 31) | (((u64)((bb >> (4*q + 1)) & 1u)) << 63);
        u64 m1 = (((u64)((bb >> (4*q + 2)) & 1u)) << 31) | (((u64)((bb >> (4*q + 3)) & 1u)) << 63);
        v[2*q]   = pack2(f.x, f.y) ^ m0;
        v[2*q+1] = pack2(f.z, f.w) ^ m1;
    }

    // ---- WHT#1a over e-bits {0,1,7,8,9} ----
    fwht32(v);

    // ---- crossing 1: natural -> QB ownership (regs become e-bits {2..6}) ----
    #pragma unroll
    for (int q = 0; q < 8; q++) {
        float a0, a1, a2, a3;
        unpack2(v[2*q],   a0, a1);
        unpack2(v[2*q+1], a2, a3);
        sA4[q * 32 + (lane ^ q)] = make_float4(a0, a1, a2, a3);   // conflict-free
    }
    __syncwarp();
    {
        const float* base = sA + qr * 128 + br;
        #pragma unroll
        for (int k = 0; k < 16; k++) {
            float a = base[((2*k)     ^ qr) << 2];   // conflict-free scalar reads
            float b = base[((2*k + 1) ^ qr) << 2];
            v[k] = pack2(a, b);
        }
    }

    // ---- WHT#1b over e-bits {2..6}: HBx complete ----
    fwht32(v);
    __syncwarp();   // all crossing-1 reads done before scatter overwrites

    // ---- crossing 2 (permutation): scatter HBx[e] to gather slot of t, P[t]=e ----
    const uint4* Qs4 = reinterpret_cast<const uint4*>(g_Qs);
    #pragma unroll
    for (int j = 0; j < 4; j++) {          // mw = 8j .. 8j+7  -> v[4j .. 4j+3]
        uint4 q = Qs4[j * 32 + lane];
        float a0, a1, a2, a3, a4, a5, a6, a7;
        unpack2(v[4*j],   a0, a1);
        unpack2(v[4*j+1], a2, a3);
        unpack2(v[4*j+2], a4, a5);
        unpack2(v[4*j+3], a6, a7);
        sA[q.x & 0xffffu] = a0;  sA[q.x >> 16] = a1;
        sA[q.y & 0xffffu] = a2;  sA[q.y >> 16] = a3;
        sA[q.z & 0xffffu] = a4;  sA[q.z >> 16] = a5;
        sA[q.w & 0xffffu] = a6;  sA[q.w >> 16] = a7;
    }
    __syncwarp();

    // ---- gather (QB ownership of t, regs = t-bits {2..6}), multiply G ----
    const float4* Gv = reinterpret_cast<const float4*>(g_Gt);
    #pragma unroll
    for (int j = 0; j < 8; j++) {
        float4 f = sA4[lane * 8 + ((j ^ lane) & 7)];   // conflict-free LDS.128
        float4 g = Gv[j * 32 + lane];                  // coalesced
        v[2*j]   = mul2(pack2(f.x, f.y), pack2(g.x, g.y));
        v[2*j+1] = mul2(pack2(f.z, f.w), pack2(g.z, g.w));
    }

    // ---- WHT#2a over t-bits {2..6} ----
    fwht32(v);
    __syncwarp();   // gather reads done before crossing-3 writes

    // ---- crossing 3: QB -> natural ownership (regs become t-bits {0,1,7,8,9}) ----
    {
        float* base = sA + qr * 128 + br;
        #pragma unroll
        for (int k = 0; k < 16; k++) {
            float a, b; unpack2(v[k], a, b);
            base[((2*k)     ^ qr) << 2] = a;   // conflict-free scalar writes
            base[((2*k + 1) ^ qr) << 2] = b;
        }
    }
    __syncwarp();
    #pragma unroll
    for (int q = 0; q < 8; q++) {
        float4 f = sA4[q * 32 + (lane ^ q)];   // conflict-free LDS.128
        v[2*q]   = pack2(f.x, f.y);
        v[2*q+1] = pack2(f.z, f.w);
    }

    // ---- WHT#2b over t-bits {0,1,7,8,9}: transform complete ----
    fwht32(v);

    // ---- x S/32 (natural table) and coalesced float4 stores ----
    const float4* Sv = reinterpret_cast<const float4*>(g_St) + lane;
    float4* ov = reinterpret_cast<float4*>(out) + (size_t)row * (D / 4) + lane;
    #pragma unroll
    for (int q = 0; q < 8; q++) {
        float4 s = Sv[q * 32];
        u64 r0 = mul2(v[2*q],   pack2(s.x, s.y));
        u64 r1 = mul2(v[2*q+1], pack2(s.z, s.w));
        float p0, p1, p2, p3;
        unpack2(r0, p0, p1);
        unpack2(r1, p2, p3);
        ov[q * 32] = make_float4(p0, p1, p2, p3);
    }
}

extern "C" void kernel_launch(void* const* d_in, const int* in_sizes, int n_in,
                              void* d_out, int out_size) {
    const float* x = (const float*)d_in[0];
    const float* B = (const float*)d_in[1];
    const float* G = (const float*)d_in[2];
    const float* S = (const float*)d_in[3];
    const int*   P = (const int*)d_in[4];
    float* out = (float*)d_out;

    const int nrows = in_sizes[0] / D;

    fastfood_prep<<<(D + 255) / 256, 256>>>(P, B, G, S);

    const int blocks = (nrows + WARPS - 1) / WARPS;
    fastfood_kernel<<<blocks, WARPS * 32>>>(x, out, nrows);
}

// round 8
// speedup vs baseline: 2.7976x; 1.1234x over previous
#include <cuda_runtime.h>
#include <cuda_fp16.h>
#include <cstdint>

#define D 1024
#define WARPS 4          // warps per block (128 threads), 1 row per warp

typedef unsigned long long u64;

// ---------- packed f32x2 helpers (sm_103a) ----------
__device__ __forceinline__ u64 pack2(float a, float b) {
    u64 r; asm("mov.b64 %0, {%1, %2};" : "=l"(r) : "f"(a), "f"(b)); return r;
}
__device__ __forceinline__ void unpack2(u64 v, float& a, float& b) {
    asm("mov.b64 {%0, %1}, %2;" : "=f"(a), "=f"(b) : "l"(v));
}
__device__ __forceinline__ u64 add2(u64 a, u64 b) {
    u64 r; asm("add.rn.f32x2 %0, %1, %2;" : "=l"(r) : "l"(a), "l"(b)); return r;
}
__device__ __forceinline__ u64 mul2(u64 a, u64 b) {
    u64 r; asm("mul.rn.f32x2 %0, %1, %2;" : "=l"(r) : "l"(a), "l"(b)); return r;
}
__device__ __forceinline__ u64 fma2(u64 a, u64 b, u64 c) {
    u64 r; asm("fma.rn.f32x2 %0, %1, %2, %3;" : "=l"(r) : "l"(a), "l"(b), "l"(c)); return r;
}
__device__ __forceinline__ unsigned h2u(__half2 h) { return *reinterpret_cast<unsigned*>(&h); }
__device__ __forceinline__ __half2 u2h(unsigned u) { return *reinterpret_cast<__half2*>(&u); }

// FWHT over the 32-value register axis. v[k] packs index i = 2k (lo), 2k+1 (hi).
__device__ __forceinline__ void fwht32(u64 v[16]) {
    const u64 NEG1 = 0xBF800000BF800000ULL;  // (-1.f, -1.f)
    #pragma unroll
    for (int k = 0; k < 16; k++) {
        float a, b; unpack2(v[k], a, b);
        v[k] = pack2(a + b, a - b);
    }
    #pragma unroll
    for (int h = 1; h <= 8; h <<= 1) {
        #pragma unroll
        for (int k = 0; k < 16; k++) {
            if (!(k & h)) {
                u64 A = v[k], B = v[k + h];
                v[k]     = add2(A, B);
                v[k + h] = fma2(B, NEG1, A);
            }
        }
    }
}

// Ownerships: "natural": lane owns z = q*128 + 4*lane + b, regs i = b|(q<<2)
// (= z-bits {0,1,7,8,9}).  "QB": lane = ((z>>7)<<2)|(z&3), regs m = (z>>2)&31.

// Precomputed tables (allocation-free scratch):
__device__ unsigned short g_Qs[D];   // scatter targets (half-slot indices)
__device__ __half         g_Gh[D];   // G[t], gather-owner layout (fp16)
__device__ __half         g_Sh[D];   // S[t]/32, natural order (fp16)
__device__ unsigned       g_Bbits[32];  // sign bits of B, natural ownership

__global__ void fastfood_prep(const int* __restrict__ P, const float* __restrict__ B,
                              const float* __restrict__ G, const float* __restrict__ S) {
    int t = blockIdx.x * blockDim.x + threadIdx.x;
    if (t < D) {
        int e  = P[t];
        int w  = ((e >> 7) << 2) | (e & 3);   // writer lane of e (QB)
        int mw = (e >> 2) & 31;               // writer reg of e
        int L  = ((t >> 7) << 2) | (t & 3);   // gather owner lane of t (QB)
        int mm = (t >> 2) & 31;               // gather reg of t
        // gather layout: lane L's 32 halves contiguous; uint2 column swizzled by (L>>1)&7
        int slot = L * 32 + ((((mm >> 2) ^ ((L >> 1) & 7)) & 7) << 2) + (mm & 3);
        g_Qs[(mw >> 3) * 256 + w * 8 + (mw & 7)] = (unsigned short)slot;
        g_Gh[((mm >> 2) * 32 + L) * 4 + (mm & 3)] = __float2half(G[t]);
        g_Sh[t] = __float2half(S[t] * 0.03125f);   // 1/sqrt(1024), SCALE=1
    }
    if (t < 32) {
        unsigned bits = 0;
        for (int q = 0; q < 8; q++)
            for (int b = 0; b < 4; b++)
                if (B[q * 128 + 4 * t + b] < 0.0f) bits |= 1u << (4 * q + b);
        g_Bbits[t] = bits;
    }
}

__global__ __launch_bounds__(WARPS * 32, 6)
void fastfood_kernel(const float* __restrict__ x, float* __restrict__ out, int nrows) {
    __shared__ __align__(16) __half buf[WARPS][D];   // 2 KB per warp, 8 KB/block
    const int warp = threadIdx.x >> 5;
    const int lane = threadIdx.x & 31;
    const int row  = blockIdx.x * WARPS + warp;
    if (row >= nrows) return;

    __half*   sh  = buf[warp];
    uint2*    sh2 = reinterpret_cast<uint2*>(sh);     // 4 halves
    unsigned* shw = reinterpret_cast<unsigned*>(sh);  // 2 halves
    const int qr = lane >> 2, br = lane & 3;

    const unsigned bb = g_Bbits[lane];

    u64 v[16];

    // ---- load x, apply B as sign-bit XOR (natural ownership of e) ----
    const float4* xv = reinterpret_cast<const float4*>(x) + (size_t)row * (D / 4) + lane;
    #pragma unroll
    for (int q = 0; q < 8; q++) {
        float4 f = xv[q * 32];
        u64 m0 = (((u64)((bb >> (4*q + 0)) & 1u)) << 31) | (((u64)((bb >> (4*q + 1)) & 1u)) << 63);
        u64 m1 = (((u64)((bb >> (4*q + 2)) & 1u)) << 31) | (((u64)((bb >> (4*q + 3)) & 1u)) << 63);
        v[2*q]   = pack2(f.x, f.y) ^ m0;
        v[2*q+1] = pack2(f.z, f.w) ^ m1;
    }

    // ---- WHT#1a over e-bits {0,1,7,8,9} ----
    fwht32(v);

    // ---- crossing 1 (fp16): natural -> QB ownership (regs become e-bits {2..6}) ----
    #pragma unroll
    for (int q = 0; q < 8; q++) {
        float a0, a1, a2, a3;
        unpack2(v[2*q],   a0, a1);
        unpack2(v[2*q+1], a2, a3);
        __half2 h01 = __floats2half2_rn(a0, a1);
        __half2 h23 = __floats2half2_rn(a2, a3);
        sh2[q * 32 + (lane ^ q)] = make_uint2(h2u(h01), h2u(h23));   // conflict-free STS.64
    }
    __syncwarp();
    {
        const __half* cbase = sh + qr * 128 + br;
        #pragma unroll
        for (int k = 0; k < 16; k++) {
            int o = ((2*k) ^ qr) << 2;
            float a = __half2float(cbase[o]);       // conflict-free LDS.16 (word broadcast)
            float b = __half2float(cbase[o ^ 4]);
            v[k] = pack2(a, b);
        }
    }

    // ---- WHT#1b over e-bits {2..6}: HBx complete ----
    fwht32(v);
    __syncwarp();   // crossing-1 reads done before scatter overwrites

    // ---- crossing 2 (permutation): fp16 scatter to gather slots ----
    const uint4* Qs4 = reinterpret_cast<const uint4*>(g_Qs);
    #pragma unroll
    for (int j = 0; j < 4; j++) {          // mw = 8j .. 8j+7  -> v[4j .. 4j+3]
        uint4 q = Qs4[j * 32 + lane];
        float a0, a1, a2, a3, a4, a5, a6, a7;
        unpack2(v[4*j],   a0, a1);
        unpack2(v[4*j+1], a2, a3);
        unpack2(v[4*j+2], a4, a5);
        unpack2(v[4*j+3], a6, a7);
        sh[q.x & 0xffffu] = __float2half_rn(a0);  sh[q.x >> 16] = __float2half_rn(a1);
        sh[q.y & 0xffffu] = __float2half_rn(a2);  sh[q.y >> 16] = __float2half_rn(a3);
        sh[q.z & 0xffffu] = __float2half_rn(a4);  sh[q.z >> 16] = __float2half_rn(a5);
        sh[q.w & 0xffffu] = __float2half_rn(a6);  sh[q.w >> 16] = __float2half_rn(a7);
    }
    __syncwarp();

    // ---- gather (QB ownership of t, regs = t-bits {2..6}), multiply G ----
    const uint2* Gv2 = reinterpret_cast<const uint2*>(g_Gh);
    #pragma unroll
    for (int j = 0; j < 8; j++) {
        uint2 f = sh2[lane * 8 + ((j ^ (lane >> 1)) & 7)];   // conflict-free LDS.64
        uint2 g = Gv2[j * 32 + lane];                        // coalesced
        float2 x01 = __half22float2(u2h(f.x)), x23 = __half22float2(u2h(f.y));
        float2 g01 = __half22float2(u2h(g.x)), g23 = __half22float2(u2h(g.y));
        v[2*j]   = mul2(pack2(x01.x, x01.y), pack2(g01.x, g01.y));
        v[2*j+1] = mul2(pack2(x23.x, x23.y), pack2(g23.x, g23.y));
    }

    // ---- WHT#2a over t-bits {2..6} ----
    fwht32(v);
    __syncwarp();   // gather reads done before crossing-3 writes

    // ---- crossing 3 (fp16): QB -> natural (regs become t-bits {0,1,7,8,9}) ----
    // write: lane ℓ's m-pairs (m=2k,2k+1) as h2 words into row ℓ, swizzled
    #pragma unroll
    for (int k = 0; k < 16; k++) {
        float a, b; unpack2(v[k], a, b);
        __half2 h = __floats2half2_rn(a, b);
        shw[lane * 16 + ((k ^ (lane >> 1)) & 15)] = h2u(h);   // conflict-free STS.32
    }
    __syncwarp();
    // read: register i = b|(q<<2) holds element t = q*128 + 4*lane + b; m(t) = lane
    #pragma unroll
    for (int kk = 0; kk < 16; kk++) {
        const int i0 = 2*kk, i1 = 2*kk + 1;
        unsigned w0 = shw[i0 * 16 + (((lane >> 1) ^ (i0 >> 1)) & 15)];  // conflict-free
        unsigned w1 = shw[i1 * 16 + (((lane >> 1) ^ (i1 >> 1)) & 15)];
        __half2 h0 = u2h(w0), h1 = u2h(w1);
        float f0 = (lane & 1) ? __high2float(h0) : __low2float(h0);
        float f1 = (lane & 1) ? __high2float(h1) : __low2float(h1);
        v[kk] = pack2(f0, f1);
    }

    // ---- WHT#2b over t-bits {0,1,7,8,9}: transform complete ----
    fwht32(v);

    // ---- x S/32 (fp16 natural table) and coalesced float4 stores ----
    const uint2* Sv2 = reinterpret_cast<const uint2*>(g_Sh);
    float4* ov = reinterpret_cast<float4*>(out) + (size_t)row * (D / 4) + lane;
    #pragma unroll
    for (int q = 0; q < 8; q++) {
        uint2 su = Sv2[q * 32 + lane];
        float2 s01 = __half22float2(u2h(su.x)), s23 = __half22float2(u2h(su.y));
        u64 r0 = mul2(v[2*q],   pack2(s01.x, s01.y));
        u64 r1 = mul2(v[2*q+1], pack2(s23.x, s23.y));
        float p0, p1, p2, p3;
        unpack2(r0, p0, p1);
        unpack2(r1, p2, p3);
        ov[q * 32] = make_float4(p0, p1, p2, p3);
    }
}

extern "C" void kernel_launch(void* const* d_in, const int* in_sizes, int n_in,
                              void* d_out, int out_size) {
    const float* x = (const float*)d_in[0];
    const float* B = (const float*)d_in[1];
    const float* G = (const float*)d_in[2];
    const float* S = (const float*)d_in[3];
    const int*   P = (const int*)d_in[4];
    float* out = (float*)d_out;

    const int nrows = in_sizes[0] / D;

    fastfood_prep<<<(D + 255) / 256, 256>>>(P, B, G, S);

    const int blocks = (nrows + WARPS - 1) / WARPS;
    fastfood_kernel<<<blocks, WARPS * 32>>>(x, out, nrows);
}

// round 9
// speedup vs baseline: 3.1776x; 1.1359x over previous
#include <cuda_runtime.h>
#include <cuda_fp16.h>
#include <cstdint>

#define D 1024
#define WARPS 4          // warps per block (128 threads), 2 rows per warp

typedef unsigned long long u64;

// ---------- packed f32x2 helpers (sm_103a) ----------
__device__ __forceinline__ u64 pack2(float a, float b) {
    u64 r; asm("mov.b64 %0, {%1, %2};" : "=l"(r) : "f"(a), "f"(b)); return r;
}
__device__ __forceinline__ void unpack2(u64 v, float& a, float& b) {
    asm("mov.b64 {%0, %1}, %2;" : "=f"(a), "=f"(b) : "l"(v));
}
__device__ __forceinline__ u64 add2(u64 a, u64 b) {
    u64 r; asm("add.rn.f32x2 %0, %1, %2;" : "=l"(r) : "l"(a), "l"(b)); return r;
}
__device__ __forceinline__ u64 mul2(u64 a, u64 b) {
    u64 r; asm("mul.rn.f32x2 %0, %1, %2;" : "=l"(r) : "l"(a), "l"(b)); return r;
}
__device__ __forceinline__ u64 fma2(u64 a, u64 b, u64 c) {
    u64 r; asm("fma.rn.f32x2 %0, %1, %2, %3;" : "=l"(r) : "l"(a), "l"(b), "l"(c)); return r;
}
__device__ __forceinline__ unsigned h2u(__half2 h) { return *reinterpret_cast<unsigned*>(&h); }
__device__ __forceinline__ __half2 u2h(unsigned u) { return *reinterpret_cast<__half2*>(&u); }
// word w = {lo: rowA, hi: rowB}
__device__ __forceinline__ unsigned mkw(float a, float b) { return h2u(__floats2half2_rn(a, b)); }
__device__ __forceinline__ float wlo(unsigned w) { return __low2float(u2h(w)); }
__device__ __forceinline__ float whi(unsigned w) { return __high2float(u2h(w)); }

// FWHT over the 32-value register axis. v[k] packs index i = 2k (lo), 2k+1 (hi).
__device__ __forceinline__ void fwht32(u64 v[16]) {
    const u64 NEG1 = 0xBF800000BF800000ULL;  // (-1.f, -1.f)
    #pragma unroll
    for (int k = 0; k < 16; k++) {
        float a, b; unpack2(v[k], a, b);
        v[k] = pack2(a + b, a - b);
    }
    #pragma unroll
    for (int h = 1; h <= 8; h <<= 1) {
        #pragma unroll
        for (int k = 0; k < 16; k++) {
            if (!(k & h)) {
                u64 A = v[k], B = v[k + h];
                v[k]     = add2(A, B);
                v[k + h] = fma2(B, NEG1, A);
            }
        }
    }
}

// Ownerships: "natural": lane owns z = q*128 + 4*lane + b, regs i = b|(q<<2)
// (= z-bits {0,1,7,8,9}).  "QB": lane = ((z>>7)<<2)|(z&3), regs m = (z>>2)&31.
// All smem in u32 words (one per element, 2 rows packed) using the verified
// R6 word-granularity conflict-free layouts.

// Precomputed tables (allocation-free scratch):
__device__ unsigned short g_Qs[D];   // scatter targets (u32-word slot indices)
__device__ __half         g_Gh[D];   // G[t], gather-owner layout (fp16)
__device__ __half         g_Sh[D];   // S[t]/32, natural order (fp16)
__device__ unsigned       g_Bbits[32];  // sign bits of B, natural ownership

__global__ void fastfood_prep(const int* __restrict__ P, const float* __restrict__ B,
                              const float* __restrict__ G, const float* __restrict__ S) {
    int t = blockIdx.x * blockDim.x + threadIdx.x;
    if (t < D) {
        int e  = P[t];
        int w  = ((e >> 7) << 2) | (e & 3);   // writer lane of e (QB)
        int mw = (e >> 2) & 31;               // writer reg of e
        int L  = ((t >> 7) << 2) | (t & 3);   // gather owner lane of t (QB)
        int mm = (t >> 2) & 31;               // gather reg of t
        // gather layout (word units): lane L's 32 words contiguous, uint4-column XOR swizzle
        int slot = L * 32 + ((((mm >> 2) ^ (L & 7)) & 7) << 2) + (mm & 3);
        g_Qs[(mw >> 3) * 256 + w * 8 + (mw & 7)] = (unsigned short)slot;
        g_Gh[((mm >> 2) * 32 + L) * 4 + (mm & 3)] = __float2half(G[t]);
        g_Sh[t] = __float2half(S[t] * 0.03125f);   // 1/sqrt(1024), SCALE=1
    }
    if (t < 32) {
        unsigned bits = 0;
        for (int q = 0; q < 8; q++)
            for (int b = 0; b < 4; b++)
                if (B[q * 128 + 4 * t + b] < 0.0f) bits |= 1u << (4 * q + b);
        g_Bbits[t] = bits;
    }
}

__global__ __launch_bounds__(WARPS * 32, 4)
void fastfood_kernel(const float* __restrict__ x, float* __restrict__ out, int nrows) {
    __shared__ __align__(16) unsigned buf[WARPS][D];   // 4 KB/warp, 16 KB/block
    const int warp = threadIdx.x >> 5;
    const int lane = threadIdx.x & 31;
    const int pair = blockIdx.x * WARPS + warp;
    if (pair * 2 >= nrows) return;

    unsigned* sw  = buf[warp];
    uint4*    sw4 = reinterpret_cast<uint4*>(sw);
    const int qr = lane >> 2, br = lane & 3;

    const unsigned bb = g_Bbits[lane];

    u64 va[16], vb[16];

    // ---- load both rows, apply B as sign-bit XOR (natural ownership of e) ----
    const float4* xa = reinterpret_cast<const float4*>(x) + (size_t)(pair * 2) * (D / 4) + lane;
    const float4* xb = xa + (D / 4);
    #pragma unroll
    for (int q = 0; q < 8; q++) {
        float4 fa = xa[q * 32];
        float4 fb = xb[q * 32];
        u64 m0 = (((u64)((bb >> (4*q + 0)) & 1u)) << 31) | (((u64)((bb >> (4*q + 1)) & 1u)) << 63);
        u64 m1 = (((u64)((bb >> (4*q + 2)) & 1u)) << 31) | (((u64)((bb >> (4*q + 3)) & 1u)) << 63);
        va[2*q]   = pack2(fa.x, fa.y) ^ m0;
        va[2*q+1] = pack2(fa.z, fa.w) ^ m1;
        vb[2*q]   = pack2(fb.x, fb.y) ^ m0;
        vb[2*q+1] = pack2(fb.z, fb.w) ^ m1;
    }

    // ---- WHT#1a over e-bits {0,1,7,8,9} ----
    fwht32(va); fwht32(vb);

    // ---- crossing 1: natural -> QB (regs become e-bits {2..6}); STS.128 words ----
    #pragma unroll
    for (int q = 0; q < 8; q++) {
        float a0, a1, a2, a3, b0, b1, b2, b3;
        unpack2(va[2*q],   a0, a1);
        unpack2(va[2*q+1], a2, a3);
        unpack2(vb[2*q],   b0, b1);
        unpack2(vb[2*q+1], b2, b3);
        sw4[q * 32 + (lane ^ q)] = make_uint4(mkw(a0,b0), mkw(a1,b1), mkw(a2,b2), mkw(a3,b3));
    }
    __syncwarp();
    {
        const unsigned* cbase = sw + qr * 128 + br;
        #pragma unroll
        for (int k = 0; k < 16; k++) {
            unsigned w0 = cbase[((2*k)     ^ qr) << 2];   // conflict-free LDS.32
            unsigned w1 = cbase[((2*k + 1) ^ qr) << 2];
            va[k] = pack2(wlo(w0), wlo(w1));
            vb[k] = pack2(whi(w0), whi(w1));
        }
    }

    // ---- WHT#1b over e-bits {2..6}: HBx complete ----
    fwht32(va); fwht32(vb);
    __syncwarp();   // crossing-1 reads done before scatter overwrites

    // ---- crossing 2 (permutation): scatter packed words to gather slots ----
    const uint4* Qs4 = reinterpret_cast<const uint4*>(g_Qs);
    #pragma unroll
    for (int j = 0; j < 4; j++) {          // mw = 8j .. 8j+7  -> v[4j .. 4j+3]
        uint4 q = Qs4[j * 32 + lane];
        float a0, a1, a2, a3, a4, a5, a6, a7;
        float b0, b1, b2, b3, b4, b5, b6, b7;
        unpack2(va[4*j],   a0, a1);  unpack2(vb[4*j],   b0, b1);
        unpack2(va[4*j+1], a2, a3);  unpack2(vb[4*j+1], b2, b3);
        unpack2(va[4*j+2], a4, a5);  unpack2(vb[4*j+2], b4, b5);
        unpack2(va[4*j+3], a6, a7);  unpack2(vb[4*j+3], b6, b7);
        sw[q.x & 0xffffu] = mkw(a0, b0);  sw[q.x >> 16] = mkw(a1, b1);
        sw[q.y & 0xffffu] = mkw(a2, b2);  sw[q.y >> 16] = mkw(a3, b3);
        sw[q.z & 0xffffu] = mkw(a4, b4);  sw[q.z >> 16] = mkw(a5, b5);
        sw[q.w & 0xffffu] = mkw(a6, b6);  sw[q.w >> 16] = mkw(a7, b7);
    }
    __syncwarp();

    // ---- gather (QB ownership of t, regs = t-bits {2..6}), multiply G ----
    const uint2* Gv2 = reinterpret_cast<const uint2*>(g_Gh);
    #pragma unroll
    for (int j = 0; j < 8; j++) {
        uint4 f = sw4[lane * 8 + ((j ^ lane) & 7)];   // conflict-free LDS.128
        uint2 g = Gv2[j * 32 + lane];                 // coalesced fp16 G
        float2 g01 = __half22float2(u2h(g.x)), g23 = __half22float2(u2h(g.y));
        u64 G01 = pack2(g01.x, g01.y), G23 = pack2(g23.x, g23.y);
        va[2*j]   = mul2(pack2(wlo(f.x), wlo(f.y)), G01);
        va[2*j+1] = mul2(pack2(wlo(f.z), wlo(f.w)), G23);
        vb[2*j]   = mul2(pack2(whi(f.x), whi(f.y)), G01);
        vb[2*j+1] = mul2(pack2(whi(f.z), whi(f.w)), G23);
    }

    // ---- WHT#2a over t-bits {2..6} ----
    fwht32(va); fwht32(vb);
    __syncwarp();   // gather reads done before crossing-3 writes

    // ---- crossing 3: QB -> natural (regs become t-bits {0,1,7,8,9}) ----
    {
        unsigned* cbase = sw + qr * 128 + br;
        #pragma unroll
        for (int k = 0; k < 16; k++) {
            float a0, a1, b0, b1;
            unpack2(va[k], a0, a1);
            unpack2(vb[k], b0, b1);
            cbase[((2*k)     ^ qr) << 2] = mkw(a0, b0);   // conflict-free STS.32
            cbase[((2*k + 1) ^ qr) << 2] = mkw(a1, b1);
        }
    }
    __syncwarp();
    #pragma unroll
    for (int q = 0; q < 8; q++) {
        uint4 f = sw4[q * 32 + (lane ^ q)];   // conflict-free LDS.128
        va[2*q]   = pack2(wlo(f.x), wlo(f.y));
        va[2*q+1] = pack2(wlo(f.z), wlo(f.w));
        vb[2*q]   = pack2(whi(f.x), whi(f.y));
        vb[2*q+1] = pack2(whi(f.z), whi(f.w));
    }

    // ---- WHT#2b over t-bits {0,1,7,8,9}: transform complete ----
    fwht32(va); fwht32(vb);

    // ---- x S/32 (fp16 natural table), coalesced float4 stores for both rows ----
    const uint2* Sv2 = reinterpret_cast<const uint2*>(g_Sh);
    float4* oa = reinterpret_cast<float4*>(out) + (size_t)(pair * 2) * (D / 4) + lane;
    float4* ob = oa + (D / 4);
    #pragma unroll
    for (int q = 0; q < 8; q++) {
        uint2 su = Sv2[q * 32 + lane];
        float2 s01 = __half22float2(u2h(su.x)), s23 = __half22float2(u2h(su.y));
        u64 S01 = pack2(s01.x, s01.y), S23 = pack2(s23.x, s23.y);
        u64 ra0 = mul2(va[2*q], S01), ra1 = mul2(va[2*q+1], S23);
        u64 rb0 = mul2(vb[2*q], S01), rb1 = mul2(vb[2*q+1], S23);
        float p0, p1, p2, p3;
        unpack2(ra0, p0, p1); unpack2(ra1, p2, p3);
        oa[q * 32] = make_float4(p0, p1, p2, p3);
        unpack2(rb0, p0, p1); unpack2(rb1, p2, p3);
        ob[q * 32] = make_float4(p0, p1, p2, p3);
    }
}

extern "C" void kernel_launch(void* const* d_in, const int* in_sizes, int n_in,
                              void* d_out, int out_size) {
    const float* x = (const float*)d_in[0];
    const float* B = (const float*)d_in[1];
    const float* G = (const float*)d_in[2];
    const float* S = (const float*)d_in[3];
    const int*   P = (const int*)d_in[4];
    float* out = (float*)d_out;

    const int nrows = in_sizes[0] / D;

    fastfood_prep<<<(D + 255) / 256, 256>>>(P, B, G, S);

    const int rows_per_block = WARPS * 2;
    const int blocks = (nrows + rows_per_block - 1) / rows_per_block;
    fastfood_kernel<<<blocks, WARPS * 32>>>(x, out, nrows);
}